// round 14
// baseline (speedup 1.0000x reference)
#include <cuda_runtime.h>
#include <math.h>

// Problem dims (fixed by the reference setup_inputs)
#define BB 4
#define LL 32
#define CC 16
#define HH 192
#define WW 192
#define HWN (HH * WW)                    // 36864
#define FLOW_ELEMS (BB * LL * 2 * HWN)   // 9,437,184
#define IMG_ELEMS  (BB * LL * CC * HWN)  // 75,497,472
#define PAD 17                           // smem row pad (floats) -> conflict-free

// Scratch (allocation-free rule: __device__ globals).
__device__ float4 g_img0[IMG_ELEMS / 4];
__device__ float4 g_img1[IMG_ELEMS / 4];
__device__ float2 g_flw0[FLOW_ELEMS / 2];
__device__ float2 g_flw1[FLOW_ELEMS / 2];

// Exact floor-mod by 2.0, value-identical to jnp.remainder(z, 2.0) in fp32.
__device__ __forceinline__ float floor_mod2(float z) {
    float q = floorf(__fmul_rn(z, 0.5f));
    return __fsub_rn(z, __fmul_rn(2.0f, q));
}

// Buffer (0/1) holding frame t's live value at the START of level k (runtime form).
__device__ __forceinline__ int parity_at(int t, int k) {
    if (t == 0) return 0;
    int f = 31 - __clz(t);
    int u = min(k, f + 1);
    return u & 1;
}

// Bit-exact coordinate/weight computation (no fma, reference association).
struct Taps {
    int i00, i01, i10, i11;
    float w00, w01, w10, w11;
};
__device__ __forceinline__ Taps make_taps(int x, int y, float f0, float f1) {
    const float C2W = (float)(2.0 / 192.0);
    const float gx = __fsub_rn(__fmul_rn(__fadd_rn((float)x, 0.5f), C2W), 1.0f);
    const float gy = __fsub_rn(__fmul_rn(__fadd_rn((float)y, 0.5f), C2W), 1.0f);

    const float fx_u = __fadd_rn(gx, f0);
    const float fy   = __fadd_rn(gy, f1);
    const float z  = __fadd_rn(fx_u, 1.0f);
    const float fx = __fsub_rn(floor_mod2(z), 1.0f);

    const float ix = __fsub_rn(__fmul_rn(__fmul_rn(__fadd_rn(fx, 1.0f), 0.5f), (float)WW), 0.5f);
    const float iy = __fsub_rn(__fmul_rn(__fmul_rn(__fadd_rn(fy, 1.0f), 0.5f), (float)HH), 0.5f);

    const float x0f = floorf(ix);
    const float y0f = floorf(iy);
    const float wx1 = __fsub_rn(ix, x0f);
    const float wy1 = __fsub_rn(iy, y0f);
    const float wx0 = __fsub_rn(1.0f, wx1);
    const float wy0 = __fsub_rn(1.0f, wy1);

    const int x0 = (int)x0f, y0 = (int)y0f;
    const int x1 = x0 + 1,  y1 = y0 + 1;

    const bool vx0 = (x0 >= 0) & (x0 < WW);
    const bool vx1 = (x1 >= 0) & (x1 < WW);
    const bool vy0 = (y0 >= 0) & (y0 < HH);
    const bool vy1 = (y1 >= 0) & (y1 < HH);

    const int xc0 = min(max(x0, 0), WW - 1);
    const int xc1 = min(max(x1, 0), WW - 1);
    const int yc0 = min(max(y0, 0), HH - 1);
    const int yc1 = min(max(y1, 0), HH - 1);

    Taps tp;
    tp.w00 = __fmul_rn(__fmul_rn(wy0, wx0), (vy0 & vx0) ? 1.0f : 0.0f);
    tp.w01 = __fmul_rn(__fmul_rn(wy0, wx1), (vy0 & vx1) ? 1.0f : 0.0f);
    tp.w10 = __fmul_rn(__fmul_rn(wy1, wx0), (vy1 & vx0) ? 1.0f : 0.0f);
    tp.w11 = __fmul_rn(__fmul_rn(wy1, wx1), (vy1 & vx1) ? 1.0f : 0.0f);
    tp.i00 = yc0 * WW + xc0;
    tp.i01 = yc0 * WW + xc1;
    tp.i10 = yc1 * WW + xc0;
    tp.i11 = yc1 * WW + xc1;
    return tp;
}

__device__ __forceinline__ int tap_sel(const Taps& tp, int j) {
    return j == 0 ? tp.i00 : (j == 1 ? tp.i01 : (j == 2 ? tp.i10 : tp.i11));
}

// Exact left-assoc weighted sum: ((w00*a + w01*b) + w10*c) + w11*d
__device__ __forceinline__ float wsum(float w00, float a, float w01, float b,
                                      float w10, float c, float w11, float d) {
    return __fadd_rn(
             __fadd_rn(
               __fadd_rn(__fmul_rn(w00, a), __fmul_rn(w01, b)),
               __fmul_rn(w10, c)),
             __fmul_rn(w11, d));
}

__device__ __forceinline__ float4 shfl_xor4_f4(float4 v) {
    const unsigned FULL = 0xffffffffu;
    float4 r;
    r.x = __shfl_xor_sync(FULL, v.x, 4);
    r.y = __shfl_xor_sync(FULL, v.y, 4);
    r.z = __shfl_xor_sync(FULL, v.z, 4);
    r.w = __shfl_xor_sync(FULL, v.w, 4);
    return r;
}

// ---------------- image transpose (NCHW input -> NHWC parity-0) ----------------

__global__ __launch_bounds__(256) void transpose_img_kernel(
    const float* __restrict__ src, float4* __restrict__ dst)
{
    __shared__ float sm[64 * PAD];
    const int px_base = blockIdx.x * 64;
    const int frame = blockIdx.y + blockIdx.z * LL;
    const float* s = src + (size_t)frame * CC * HWN;

    #pragma unroll
    for (int it = 0; it < 4; it++) {
        const int li = it * 256 + threadIdx.x;
        const int px = li & 63;
        const int ch = li >> 6;
        sm[px * PAD + ch] = s[ch * HWN + px_base + px];
    }
    __syncthreads();

    const int px = threadIdx.x >> 2;
    const int cq = threadIdx.x & 3;
    float4 v;
    v.x = sm[px * PAD + cq * 4 + 0];
    v.y = sm[px * PAD + cq * 4 + 1];
    v.z = sm[px * PAD + cq * 4 + 2];
    v.w = sm[px * PAD + cq * 4 + 3];
    dst[(size_t)frame * HWN * 4 + (px_base + px) * 4 + cq] = v;
}

// -------- scan step: merged taps + compile-time cur parity + dead-flow skip -----
// Group of 8 lanes handles 2 pixels. half = s>>2, q = s&3. Image tap loads cover
// x-adjacent (left,right) 64B chunks -> contiguous 128B per group; exchange via
// shfl_xor(4). Per-lane arithmetic on its OWN pixel, exact left-assoc non-fma.
// Cur parity == K&1 (compile-time, valid for all launched t >= 2^K).
// RAW=true (level 0 only): flow reads come straight from the NCHW input
// (transpose_flow deleted — proven dead).
// Flow updates are computed only for t >= 2*STEP (proven dead otherwise; all
// flow values ever read then have complete update history -> parity fold exact).

template <int K, int STEP, bool RAW>
__global__ __launch_bounds__(256, 5) void pscan_step(
    float2* flw0, float2* flw1, float4* img0, float4* img1,
    const float* __restrict__ rawFlw)
{
    constexpr int PC = K & 1;                   // cur parity (compile-time)
    const unsigned FULL = 0xffffffffu;
    const int t   = blockIdx.y + STEP;          // only frames t >= STEP launched
    const int bz  = blockIdx.z;
    const int tid = threadIdx.x;
    const int s    = tid & 7;
    const int half = s >> 2;
    const int q    = s & 3;
    const int k    = (tid >> 3) & 3;            // group within warp
    const int wbase = blockIdx.x * 128 + (tid >> 5) * 8;  // slot-0 warp pixel base

    const int frame = bz * LL + t;
    const int prevf = frame - STEP;
    const int pp = parity_at(t - STEP, K);      // prev parity (runtime)

    const bool doFlow = (t >= 2 * STEP);        // uniform per block

    const float2* fcur  = (PC ? flw1 : flw0) + (size_t)frame * HWN;
    const float4* icur  = (PC ? img1 : img0) + (size_t)frame * (HWN * 4);
    float2*       fdst  = (PC ? flw0 : flw1) + (size_t)frame * HWN;
    float4*       idst  = (PC ? img0 : img1) + (size_t)frame * (HWN * 4);
    const float2* fprev = (pp ? flw1 : flw0) + (size_t)prevf * HWN;
    const float4* iprev = (pp ? img1 : img0) + (size_t)prevf * (HWN * 4);

    const float* rawCur  = RAW ? (rawFlw + (size_t)frame * 2 * HWN) : nullptr;
    const float* rawPrev = RAW ? (rawFlw + (size_t)prevf * 2 * HWN) : nullptr;

    #pragma unroll
    for (int slot = 0; slot < 2; slot++) {
        const int base = wbase + slot * 64;
        const int pxO  = base + half * 4 + k;   // owned pixel

        float2 fcO;
        if (RAW) {
            fcO.x = __ldg(&rawCur[pxO]);
            fcO.y = __ldg(&rawCur[HWN + pxO]);
        } else {
            fcO = __ldg(&fcur[pxO]);
        }
        const Taps tpO = make_taps(pxO % WW, pxO / WW, fcO.x, fcO.y);

        // index exchange: send what partner needs for its cross-pixel row loads
        const int idxs0 = __shfl_xor_sync(FULL, half ? tpO.i00 : tpO.i01, 4);
        const int idxs1 = __shfl_xor_sync(FULL, half ? tpO.i10 : tpO.i11, 4);

        // row-pair image tap loads (each group instruction = contiguous 128B)
        const float4 rowA0 = __ldg(&iprev[(half ? idxs0   : tpO.i00) * 4 + q]);
        const float4 rowA1 = __ldg(&iprev[(half ? idxs1   : tpO.i10) * 4 + q]);
        const float4 rowB0 = __ldg(&iprev[(half ? tpO.i01 : idxs0  ) * 4 + q]);
        const float4 rowB1 = __ldg(&iprev[(half ? tpO.i11 : idxs1  ) * 4 + q]);
        const float4 c     = __ldg(&icur[pxO * 4 + q]);

        // value exchange: send the half the partner's output needs
        const float4 opp0 = shfl_xor4_f4(half ? rowA0 : rowB0);
        const float4 opp1 = shfl_xor4_f4(half ? rowA1 : rowB1);

        const float4 t00 = half ? opp0  : rowA0;
        const float4 t01 = half ? rowB0 : opp0;
        const float4 t10 = half ? opp1  : rowA1;
        const float4 t11 = half ? rowB1 : opp1;

        float4 o;
        o.x = __fadd_rn(c.x, wsum(tpO.w00, t00.x, tpO.w01, t01.x, tpO.w10, t10.x, tpO.w11, t11.x));
        o.y = __fadd_rn(c.y, wsum(tpO.w00, t00.y, tpO.w01, t01.y, tpO.w10, t10.y, tpO.w11, t11.y));
        o.z = __fadd_rn(c.z, wsum(tpO.w00, t00.z, tpO.w01, t01.z, tpO.w10, t10.z, tpO.w11, t11.z));
        o.w = __fadd_rn(c.w, wsum(tpO.w00, t00.w, tpO.w01, t01.w, tpO.w10, t10.w, tpO.w11, t11.w));
        idst[pxO * 4 + q] = o;

        // flow path only when the output is live (uniform branch; shfl warp-uniform)
        if (doFlow) {
            float2 ftap;
            const int ti = tap_sel(tpO, q);
            if (RAW) {
                ftap.x = __ldg(&rawPrev[ti]);
                ftap.y = __ldg(&rawPrev[HWN + ti]);
            } else {
                ftap = __ldg(&fprev[ti]);
            }
            const float f01x = __shfl_down_sync(FULL, ftap.x, 1);
            const float f01y = __shfl_down_sync(FULL, ftap.y, 1);
            const float f10x = __shfl_down_sync(FULL, ftap.x, 2);
            const float f10y = __shfl_down_sync(FULL, ftap.y, 2);
            const float f11x = __shfl_down_sync(FULL, ftap.x, 3);
            const float f11y = __shfl_down_sync(FULL, ftap.y, 3);
            if (q == 0) {
                float2 of;
                of.x = __fadd_rn(fcO.x, wsum(tpO.w00, ftap.x, tpO.w01, f01x, tpO.w10, f10x, tpO.w11, f11x));
                of.y = __fadd_rn(fcO.y, wsum(tpO.w00, ftap.y, tpO.w01, f01y, tpO.w10, f10y, tpO.w11, f11y));
                fdst[pxO] = of;
            }
        }
    }
}

// final level (K=4, STEP=16): compute in NHWC, smem-stage, coalesced NCHW writeback.
__global__ __launch_bounds__(256, 5) void pscan_final(
    float2* flw0, float2* flw1, float4* img0, float4* img1,
    float* __restrict__ out)
{
    __shared__ float sm[128 * PAD];

    const int t   = blockIdx.y;
    const int bz  = blockIdx.z;
    const int tid = threadIdx.x;
    const int cq  = tid & 3;
    const int px_base = blockIdx.x * 128;
    const int p0l = tid >> 2;
    const int p1l = p0l + 64;
    const int px0 = px_base + p0l;
    const int px1 = px_base + p1l;

    const int frame = bz * LL + t;
    const int pc = parity_at(t, 4);
    const float4* icur = (pc ? img1 : img0) + (size_t)frame * (HWN * 4);

    float4 o0, o1;

    if (t < 16) {
        o0 = __ldg(&icur[px0 * 4 + cq]);
        o1 = __ldg(&icur[px1 * 4 + cq]);
    } else {
        const int prevf = frame - 16;
        const int pp = parity_at(t - 16, 4);
        const float2* fcur  = (pc ? flw1 : flw0) + (size_t)frame * HWN;
        const float4* iprev = (pp ? img1 : img0) + (size_t)prevf * (HWN * 4);

        const float2 fc0 = __ldg(&fcur[px0]);
        const float2 fc1 = __ldg(&fcur[px1]);
        const Taps tp0 = make_taps(px0 % WW, px0 / WW, fc0.x, fc0.y);
        const Taps tp1 = make_taps(px1 % WW, px1 / WW, fc1.x, fc1.y);

        const float4 a00 = __ldg(&iprev[tp0.i00 * 4 + cq]);
        const float4 a01 = __ldg(&iprev[tp0.i01 * 4 + cq]);
        const float4 a10 = __ldg(&iprev[tp0.i10 * 4 + cq]);
        const float4 a11 = __ldg(&iprev[tp0.i11 * 4 + cq]);
        const float4 e00 = __ldg(&iprev[tp1.i00 * 4 + cq]);
        const float4 e01 = __ldg(&iprev[tp1.i01 * 4 + cq]);
        const float4 e10 = __ldg(&iprev[tp1.i10 * 4 + cq]);
        const float4 e11 = __ldg(&iprev[tp1.i11 * 4 + cq]);
        const float4 c0  = __ldg(&icur[px0 * 4 + cq]);
        const float4 c1  = __ldg(&icur[px1 * 4 + cq]);

        o0.x = __fadd_rn(c0.x, wsum(tp0.w00, a00.x, tp0.w01, a01.x, tp0.w10, a10.x, tp0.w11, a11.x));
        o0.y = __fadd_rn(c0.y, wsum(tp0.w00, a00.y, tp0.w01, a01.y, tp0.w10, a10.y, tp0.w11, a11.y));
        o0.z = __fadd_rn(c0.z, wsum(tp0.w00, a00.z, tp0.w01, a01.z, tp0.w10, a10.z, tp0.w11, a11.z));
        o0.w = __fadd_rn(c0.w, wsum(tp0.w00, a00.w, tp0.w01, a01.w, tp0.w10, a10.w, tp0.w11, a11.w));
        o1.x = __fadd_rn(c1.x, wsum(tp1.w00, e00.x, tp1.w01, e01.x, tp1.w10, e10.x, tp1.w11, e11.x));
        o1.y = __fadd_rn(c1.y, wsum(tp1.w00, e00.y, tp1.w01, e01.y, tp1.w10, e10.y, tp1.w11, e11.y));
        o1.z = __fadd_rn(c1.z, wsum(tp1.w00, e00.z, tp1.w01, e01.z, tp1.w10, e10.z, tp1.w11, e11.z));
        o1.w = __fadd_rn(c1.w, wsum(tp1.w00, e00.w, tp1.w01, e01.w, tp1.w10, e10.w, tp1.w11, e11.w));
    }

    sm[p0l * PAD + cq * 4 + 0] = o0.x;
    sm[p0l * PAD + cq * 4 + 1] = o0.y;
    sm[p0l * PAD + cq * 4 + 2] = o0.z;
    sm[p0l * PAD + cq * 4 + 3] = o0.w;
    sm[p1l * PAD + cq * 4 + 0] = o1.x;
    sm[p1l * PAD + cq * 4 + 1] = o1.y;
    sm[p1l * PAD + cq * 4 + 2] = o1.z;
    sm[p1l * PAD + cq * 4 + 3] = o1.w;
    __syncthreads();

    float* dimg = out + (size_t)frame * CC * HWN;
    #pragma unroll
    for (int it = 0; it < 8; it++) {
        const int li = it * 256 + tid;
        const int ch = li >> 7;
        const int px = li & 127;
        dimg[ch * HWN + px_base + px] = sm[px * PAD + ch];
    }
}

extern "C" void kernel_launch(void* const* d_in, const int* in_sizes, int n_in,
                              void* d_out, int out_size)
{
    const float* in_flows  = (const float*)d_in[0];  // [B,L,2,H,W]
    const float* in_images = (const float*)d_in[1];  // [B,L,C,H,W]
    if (in_sizes[0] == IMG_ELEMS && in_sizes[1] == FLOW_ELEMS) {
        in_flows  = (const float*)d_in[1];
        in_images = (const float*)d_in[0];
    }
    float* out_images = (float*)d_out;               // [B,L,C,H,W]

    float4 *i0, *i1;
    float2 *f0, *f1;
    cudaGetSymbolAddress((void**)&i0, g_img0);
    cudaGetSymbolAddress((void**)&i1, g_img1);
    cudaGetSymbolAddress((void**)&f0, g_flw0);
    cudaGetSymbolAddress((void**)&f1, g_flw1);

    dim3 block(256);

    // image transpose only (flow transpose proven dead: level 0 reads raw NCHW)
    {
        dim3 gridI(HWN / 64, LL, BB);
        transpose_img_kernel<<<gridI, block>>>(in_images, i0);
    }

    {
        dim3 g1(HWN / 128, LL - 1, BB);
        pscan_step<0, 1, true><<<g1, block>>>(f0, f1, i0, i1, in_flows);
        dim3 g2(HWN / 128, LL - 2, BB);
        pscan_step<1, 2, false><<<g2, block>>>(f0, f1, i0, i1, nullptr);
        dim3 g4(HWN / 128, LL - 4, BB);
        pscan_step<2, 4, false><<<g4, block>>>(f0, f1, i0, i1, nullptr);
        dim3 g8(HWN / 128, LL - 8, BB);
        pscan_step<3, 8, false><<<g8, block>>>(f0, f1, i0, i1, nullptr);
    }

    {
        dim3 gf(HWN / 128, LL, BB);
        pscan_final<<<gf, block>>>(f0, f1, i0, i1, out_images);
    }
}

// round 15
// speedup vs baseline: 1.0669x; 1.0669x over previous
#include <cuda_runtime.h>
#include <math.h>

// Problem dims (fixed by the reference setup_inputs)
#define BB 4
#define LL 32
#define CC 16
#define HH 192
#define WW 192
#define HWN (HH * WW)                    // 36864
#define FLOW_ELEMS (BB * LL * 2 * HWN)   // 9,437,184
#define IMG_ELEMS  (BB * LL * CC * HWN)  // 75,497,472
#define PAD 17                           // smem row pad (floats) -> conflict-free

// Scratch (allocation-free rule: __device__ globals).
__device__ float4 g_img0[IMG_ELEMS / 4];
__device__ float4 g_img1[IMG_ELEMS / 4];
__device__ float2 g_flw0[FLOW_ELEMS / 2];
__device__ float2 g_flw1[FLOW_ELEMS / 2];

// Exact floor-mod by 2.0, value-identical to jnp.remainder(z, 2.0) in fp32.
__device__ __forceinline__ float floor_mod2(float z) {
    float q = floorf(__fmul_rn(z, 0.5f));
    return __fsub_rn(z, __fmul_rn(2.0f, q));
}

// Buffer (0/1) holding frame t's live value at the START of level k (runtime form).
__device__ __forceinline__ int parity_at(int t, int k) {
    if (t == 0) return 0;
    int f = 31 - __clz(t);
    int u = min(k, f + 1);
    return u & 1;
}

// Bit-exact coordinate/weight computation (no fma, reference association).
struct Taps {
    int i00, i01, i10, i11;
    float w00, w01, w10, w11;
};
__device__ __forceinline__ Taps make_taps(int x, int y, float f0, float f1) {
    const float C2W = (float)(2.0 / 192.0);
    const float gx = __fsub_rn(__fmul_rn(__fadd_rn((float)x, 0.5f), C2W), 1.0f);
    const float gy = __fsub_rn(__fmul_rn(__fadd_rn((float)y, 0.5f), C2W), 1.0f);

    const float fx_u = __fadd_rn(gx, f0);
    const float fy   = __fadd_rn(gy, f1);
    const float z  = __fadd_rn(fx_u, 1.0f);
    const float fx = __fsub_rn(floor_mod2(z), 1.0f);

    const float ix = __fsub_rn(__fmul_rn(__fmul_rn(__fadd_rn(fx, 1.0f), 0.5f), (float)WW), 0.5f);
    const float iy = __fsub_rn(__fmul_rn(__fmul_rn(__fadd_rn(fy, 1.0f), 0.5f), (float)HH), 0.5f);

    const float x0f = floorf(ix);
    const float y0f = floorf(iy);
    const float wx1 = __fsub_rn(ix, x0f);
    const float wy1 = __fsub_rn(iy, y0f);
    const float wx0 = __fsub_rn(1.0f, wx1);
    const float wy0 = __fsub_rn(1.0f, wy1);

    const int x0 = (int)x0f, y0 = (int)y0f;
    const int x1 = x0 + 1,  y1 = y0 + 1;

    const bool vx0 = (x0 >= 0) & (x0 < WW);
    const bool vx1 = (x1 >= 0) & (x1 < WW);
    const bool vy0 = (y0 >= 0) & (y0 < HH);
    const bool vy1 = (y1 >= 0) & (y1 < HH);

    const int xc0 = min(max(x0, 0), WW - 1);
    const int xc1 = min(max(x1, 0), WW - 1);
    const int yc0 = min(max(y0, 0), HH - 1);
    const int yc1 = min(max(y1, 0), HH - 1);

    Taps tp;
    tp.w00 = __fmul_rn(__fmul_rn(wy0, wx0), (vy0 & vx0) ? 1.0f : 0.0f);
    tp.w01 = __fmul_rn(__fmul_rn(wy0, wx1), (vy0 & vx1) ? 1.0f : 0.0f);
    tp.w10 = __fmul_rn(__fmul_rn(wy1, wx0), (vy1 & vx0) ? 1.0f : 0.0f);
    tp.w11 = __fmul_rn(__fmul_rn(wy1, wx1), (vy1 & vx1) ? 1.0f : 0.0f);
    tp.i00 = yc0 * WW + xc0;
    tp.i01 = yc0 * WW + xc1;
    tp.i10 = yc1 * WW + xc0;
    tp.i11 = yc1 * WW + xc1;
    return tp;
}

__device__ __forceinline__ int tap_sel(const Taps& tp, int j) {
    return j == 0 ? tp.i00 : (j == 1 ? tp.i01 : (j == 2 ? tp.i10 : tp.i11));
}

// Exact left-assoc weighted sum: ((w00*a + w01*b) + w10*c) + w11*d
__device__ __forceinline__ float wsum(float w00, float a, float w01, float b,
                                      float w10, float c, float w11, float d) {
    return __fadd_rn(
             __fadd_rn(
               __fadd_rn(__fmul_rn(w00, a), __fmul_rn(w01, b)),
               __fmul_rn(w10, c)),
             __fmul_rn(w11, d));
}

__device__ __forceinline__ float4 shfl_xor4_f4(float4 v) {
    const unsigned FULL = 0xffffffffu;
    float4 r;
    r.x = __shfl_xor_sync(FULL, v.x, 4);
    r.y = __shfl_xor_sync(FULL, v.y, 4);
    r.z = __shfl_xor_sync(FULL, v.z, 4);
    r.w = __shfl_xor_sync(FULL, v.w, 4);
    return r;
}

// ---------------- transpose kernels (inputs -> parity-0 buffers) ----------------

__global__ __launch_bounds__(256) void transpose_img_kernel(
    const float* __restrict__ src, float4* __restrict__ dst)
{
    __shared__ float sm[64 * PAD];
    const int px_base = blockIdx.x * 64;
    const int frame = blockIdx.y + blockIdx.z * LL;
    const float* s = src + (size_t)frame * CC * HWN;

    #pragma unroll
    for (int it = 0; it < 4; it++) {
        const int li = it * 256 + threadIdx.x;
        const int px = li & 63;
        const int ch = li >> 6;
        sm[px * PAD + ch] = s[ch * HWN + px_base + px];
    }
    __syncthreads();

    const int px = threadIdx.x >> 2;
    const int cq = threadIdx.x & 3;
    float4 v;
    v.x = sm[px * PAD + cq * 4 + 0];
    v.y = sm[px * PAD + cq * 4 + 1];
    v.z = sm[px * PAD + cq * 4 + 2];
    v.w = sm[px * PAD + cq * 4 + 3];
    dst[(size_t)frame * HWN * 4 + (px_base + px) * 4 + cq] = v;
}

__global__ __launch_bounds__(256) void transpose_flow_kernel(
    const float* __restrict__ src, float2* __restrict__ dst)
{
    const int px = blockIdx.x * blockDim.x + threadIdx.x;
    const int frame = blockIdx.y + blockIdx.z * LL;
    const float* s = src + (size_t)frame * 2 * HWN;
    float2 v;
    v.x = s[px];
    v.y = s[HWN + px];
    dst[(size_t)frame * HWN + px] = v;
}

// -------- scan step: R10 merged-tap structure + compile-time cur parity --------
// Group of 8 lanes handles 2 pixels (A = base+k, B = base+4+k). half = s>>2,
// q = s&3. Image tap loads arranged so each group's 8 lanes cover one pixel's
// x-adjacent (left,right) 64B chunks -> contiguous 128B per group. Values and
// indices exchanged with shfl_xor(4); per-lane arithmetic on its OWN pixel uses
// the exact left-associative non-fma chain (bit-exact). For launched frames
// t >= 2^K, u(t,K) == K, so cur parity == K&1 at compile time.

template <int K, int STEP>
__global__ __launch_bounds__(256, 5) void pscan_step(
    float2* flw0, float2* flw1, float4* img0, float4* img1)
{
    constexpr int PC = K & 1;                   // cur parity (compile-time)
    const unsigned FULL = 0xffffffffu;
    const int t   = blockIdx.y + STEP;          // only frames t >= STEP launched
    const int bz  = blockIdx.z;
    const int tid = threadIdx.x;
    const int s    = tid & 7;
    const int half = s >> 2;
    const int q    = s & 3;
    const int k    = (tid >> 3) & 3;            // group within warp
    const int wbase = blockIdx.x * 128 + (tid >> 5) * 8;  // slot-0 warp pixel base

    const int frame = bz * LL + t;
    const int prevf = frame - STEP;
    const int pp = parity_at(t - STEP, K);      // prev parity (runtime)

    const float2* fcur  = (PC ? flw1 : flw0) + (size_t)frame * HWN;
    const float4* icur  = (PC ? img1 : img0) + (size_t)frame * (HWN * 4);
    float2*       fdst  = (PC ? flw0 : flw1) + (size_t)frame * HWN;
    float4*       idst  = (PC ? img0 : img1) + (size_t)frame * (HWN * 4);
    const float2* fprev = (pp ? flw1 : flw0) + (size_t)prevf * HWN;
    const float4* iprev = (pp ? img1 : img0) + (size_t)prevf * (HWN * 4);

    #pragma unroll
    for (int slot = 0; slot < 2; slot++) {
        const int base = wbase + slot * 64;
        const int pxO  = base + half * 4 + k;   // owned pixel (A for half=0, B for half=1)

        const float2 fcO = __ldg(&fcur[pxO]);
        const Taps tpO = make_taps(pxO % WW, pxO / WW, fcO.x, fcO.y);

        // index exchange: send what partner needs for its cross-pixel row loads
        const int idxs0 = __shfl_xor_sync(FULL, half ? tpO.i00 : tpO.i01, 4);
        const int idxs1 = __shfl_xor_sync(FULL, half ? tpO.i10 : tpO.i11, 4);
        // half=0 received: i00B, i10B   half=1 received: i01A, i11A

        // row-pair image tap loads (each group instruction = contiguous 128B)
        const float4 rowA0 = __ldg(&iprev[(half ? idxs0   : tpO.i00) * 4 + q]);
        const float4 rowA1 = __ldg(&iprev[(half ? idxs1   : tpO.i10) * 4 + q]);
        const float4 rowB0 = __ldg(&iprev[(half ? tpO.i01 : idxs0  ) * 4 + q]);
        const float4 rowB1 = __ldg(&iprev[(half ? tpO.i11 : idxs1  ) * 4 + q]);
        const float4 c     = __ldg(&icur[pxO * 4 + q]);
        // flow tap: lane q loads its own pixel's tap q
        const float2 ftap  = __ldg(&fprev[tap_sel(tpO, q)]);

        // value exchange: send the half the partner's output needs
        const float4 opp0 = shfl_xor4_f4(half ? rowA0 : rowB0);
        const float4 opp1 = shfl_xor4_f4(half ? rowA1 : rowB1);

        const float4 t00 = half ? opp0  : rowA0;
        const float4 t01 = half ? rowB0 : opp0;
        const float4 t10 = half ? opp1  : rowA1;
        const float4 t11 = half ? rowB1 : opp1;

        float4 o;
        o.x = __fadd_rn(c.x, wsum(tpO.w00, t00.x, tpO.w01, t01.x, tpO.w10, t10.x, tpO.w11, t11.x));
        o.y = __fadd_rn(c.y, wsum(tpO.w00, t00.y, tpO.w01, t01.y, tpO.w10, t10.y, tpO.w11, t11.y));
        o.z = __fadd_rn(c.z, wsum(tpO.w00, t00.z, tpO.w01, t01.z, tpO.w10, t10.z, tpO.w11, t11.z));
        o.w = __fadd_rn(c.w, wsum(tpO.w00, t00.w, tpO.w01, t01.w, tpO.w10, t10.w, tpO.w11, t11.w));
        idst[pxO * 4 + q] = o;

        // flow output on lane q==0 of each half (own pixel's 4 taps from lanes q..q+3)
        const float f01x = __shfl_down_sync(FULL, ftap.x, 1);
        const float f01y = __shfl_down_sync(FULL, ftap.y, 1);
        const float f10x = __shfl_down_sync(FULL, ftap.x, 2);
        const float f10y = __shfl_down_sync(FULL, ftap.y, 2);
        const float f11x = __shfl_down_sync(FULL, ftap.x, 3);
        const float f11y = __shfl_down_sync(FULL, ftap.y, 3);
        if (q == 0) {
            float2 of;
            of.x = __fadd_rn(fcO.x, wsum(tpO.w00, ftap.x, tpO.w01, f01x, tpO.w10, f10x, tpO.w11, f11x));
            of.y = __fadd_rn(fcO.y, wsum(tpO.w00, ftap.y, tpO.w01, f01y, tpO.w10, f10y, tpO.w11, f11y));
            fdst[pxO] = of;
        }
    }
}

// final level (K=4, STEP=16): compute in NHWC, smem-stage, coalesced NCHW writeback.
// Output stores use __stcs (evict-first): d_out is never read again, so keep L2
// for this kernel's own gather lines.
__global__ __launch_bounds__(256, 5) void pscan_final(
    float2* flw0, float2* flw1, float4* img0, float4* img1,
    float* __restrict__ out)
{
    __shared__ float sm[128 * PAD];

    const int t   = blockIdx.y;
    const int bz  = blockIdx.z;
    const int tid = threadIdx.x;
    const int cq  = tid & 3;
    const int px_base = blockIdx.x * 128;
    const int p0l = tid >> 2;
    const int p1l = p0l + 64;
    const int px0 = px_base + p0l;
    const int px1 = px_base + p1l;

    const int frame = bz * LL + t;
    const int pc = parity_at(t, 4);
    const float4* icur = (pc ? img1 : img0) + (size_t)frame * (HWN * 4);

    float4 o0, o1;

    if (t < 16) {
        o0 = __ldg(&icur[px0 * 4 + cq]);
        o1 = __ldg(&icur[px1 * 4 + cq]);
    } else {
        const int prevf = frame - 16;
        const int pp = parity_at(t - 16, 4);
        const float2* fcur  = (pc ? flw1 : flw0) + (size_t)frame * HWN;
        const float4* iprev = (pp ? img1 : img0) + (size_t)prevf * (HWN * 4);

        const float2 fc0 = __ldg(&fcur[px0]);
        const float2 fc1 = __ldg(&fcur[px1]);
        const Taps tp0 = make_taps(px0 % WW, px0 / WW, fc0.x, fc0.y);
        const Taps tp1 = make_taps(px1 % WW, px1 / WW, fc1.x, fc1.y);

        const float4 a00 = __ldg(&iprev[tp0.i00 * 4 + cq]);
        const float4 a01 = __ldg(&iprev[tp0.i01 * 4 + cq]);
        const float4 a10 = __ldg(&iprev[tp0.i10 * 4 + cq]);
        const float4 a11 = __ldg(&iprev[tp0.i11 * 4 + cq]);
        const float4 e00 = __ldg(&iprev[tp1.i00 * 4 + cq]);
        const float4 e01 = __ldg(&iprev[tp1.i01 * 4 + cq]);
        const float4 e10 = __ldg(&iprev[tp1.i10 * 4 + cq]);
        const float4 e11 = __ldg(&iprev[tp1.i11 * 4 + cq]);
        const float4 c0  = __ldg(&icur[px0 * 4 + cq]);
        const float4 c1  = __ldg(&icur[px1 * 4 + cq]);

        o0.x = __fadd_rn(c0.x, wsum(tp0.w00, a00.x, tp0.w01, a01.x, tp0.w10, a10.x, tp0.w11, a11.x));
        o0.y = __fadd_rn(c0.y, wsum(tp0.w00, a00.y, tp0.w01, a01.y, tp0.w10, a10.y, tp0.w11, a11.y));
        o0.z = __fadd_rn(c0.z, wsum(tp0.w00, a00.z, tp0.w01, a01.z, tp0.w10, a10.z, tp0.w11, a11.z));
        o0.w = __fadd_rn(c0.w, wsum(tp0.w00, a00.w, tp0.w01, a01.w, tp0.w10, a10.w, tp0.w11, a11.w));
        o1.x = __fadd_rn(c1.x, wsum(tp1.w00, e00.x, tp1.w01, e01.x, tp1.w10, e10.x, tp1.w11, e11.x));
        o1.y = __fadd_rn(c1.y, wsum(tp1.w00, e00.y, tp1.w01, e01.y, tp1.w10, e10.y, tp1.w11, e11.y));
        o1.z = __fadd_rn(c1.z, wsum(tp1.w00, e00.z, tp1.w01, e01.z, tp1.w10, e10.z, tp1.w11, e11.z));
        o1.w = __fadd_rn(c1.w, wsum(tp1.w00, e00.w, tp1.w01, e01.w, tp1.w10, e10.w, tp1.w11, e11.w));
    }

    sm[p0l * PAD + cq * 4 + 0] = o0.x;
    sm[p0l * PAD + cq * 4 + 1] = o0.y;
    sm[p0l * PAD + cq * 4 + 2] = o0.z;
    sm[p0l * PAD + cq * 4 + 3] = o0.w;
    sm[p1l * PAD + cq * 4 + 0] = o1.x;
    sm[p1l * PAD + cq * 4 + 1] = o1.y;
    sm[p1l * PAD + cq * 4 + 2] = o1.z;
    sm[p1l * PAD + cq * 4 + 3] = o1.w;
    __syncthreads();

    float* dimg = out + (size_t)frame * CC * HWN;
    #pragma unroll
    for (int it = 0; it < 8; it++) {
        const int li = it * 256 + tid;
        const int ch = li >> 7;
        const int px = li & 127;
        __stcs(&dimg[ch * HWN + px_base + px], sm[px * PAD + ch]);
    }
}

extern "C" void kernel_launch(void* const* d_in, const int* in_sizes, int n_in,
                              void* d_out, int out_size)
{
    const float* in_flows  = (const float*)d_in[0];  // [B,L,2,H,W]
    const float* in_images = (const float*)d_in[1];  // [B,L,C,H,W]
    if (in_sizes[0] == IMG_ELEMS && in_sizes[1] == FLOW_ELEMS) {
        in_flows  = (const float*)d_in[1];
        in_images = (const float*)d_in[0];
    }
    float* out_images = (float*)d_out;               // [B,L,C,H,W]

    float4 *i0, *i1;
    float2 *f0, *f1;
    cudaGetSymbolAddress((void**)&i0, g_img0);
    cudaGetSymbolAddress((void**)&i1, g_img1);
    cudaGetSymbolAddress((void**)&f0, g_flw0);
    cudaGetSymbolAddress((void**)&f1, g_flw1);

    dim3 block(256);

    {
        dim3 gridI(HWN / 64, LL, BB);
        transpose_img_kernel<<<gridI, block>>>(in_images, i0);
        dim3 gridF(HWN / 256, LL, BB);
        transpose_flow_kernel<<<gridF, block>>>(in_flows, f0);
    }

    {
        dim3 g1(HWN / 128, LL - 1, BB);
        pscan_step<0, 1><<<g1, block>>>(f0, f1, i0, i1);
        dim3 g2(HWN / 128, LL - 2, BB);
        pscan_step<1, 2><<<g2, block>>>(f0, f1, i0, i1);
        dim3 g4(HWN / 128, LL - 4, BB);
        pscan_step<2, 4><<<g4, block>>>(f0, f1, i0, i1);
        dim3 g8(HWN / 128, LL - 8, BB);
        pscan_step<3, 8><<<g8, block>>>(f0, f1, i0, i1);
    }

    {
        dim3 gf(HWN / 128, LL, BB);
        pscan_final<<<gf, block>>>(f0, f1, i0, i1, out_images);
    }
}